// round 14
// baseline (speedup 1.0000x reference)
#include <cuda_runtime.h>
#include <cstddef>

#define TB 64
#define TT 1024
#define TI 64
#define TH 512
#define TR 8
#define TO 64

typedef unsigned long long ull;

// combined drive d = 0.05*noise + 0.2*(u@W_in^T + b_in), layout [T,B,H]
__device__ float g_drv[(size_t)TT * TB * TH];
// unified state buffer: rows 0..63 = x0; row 64+(t*B+b) = x̃ after step t
__device__ float g_X[((size_t)TT * TB + TB) * TH];
// 16 dots at state BEFORE step t, row m=t*B+b: g_c1[m*16+d]; d<8: r@M, d>=8: r@N
__device__ float g_c1[(size_t)TT * TB * 16];
// scanned products: g_q[(b*T+t)*8 + j]
__device__ float g_q[(size_t)TB * TT * 8];

__device__ __forceinline__ float fast_tanh(float x) {
    float y;
    asm("tanh.approx.f32 %0, %1;" : "=f"(y) : "f"(x));
    return y;
}
__device__ __forceinline__ float acc_tanh(float x) {
    float e;
    asm("ex2.approx.f32 %0, %1;" : "=f"(e) : "f"(x * 2.8853900817779268f));
    float d;
    asm("rcp.approx.f32 %0, %1;" : "=f"(d) : "f"(e + 1.0f));
    return fmaf(-2.0f, d, 1.0f);
}
__device__ __forceinline__ void fma2(ull& acc, ull a, ull b) {
    asm("fma.rn.f32x2 %0, %1, %2, %0;" : "+l"(acc) : "l"(a), "l"(b));
}
__device__ __forceinline__ ull dup2(float a) {
    ull d;
    asm("mov.b64 %0, {%1, %1};" : "=l"(d) : "f"(a));
    return d;
}
__device__ __forceinline__ void unpack2(ull v, float& lo, float& hi) {
    asm("mov.b64 {%0, %1}, %2;" : "=f"(lo), "=f"(hi) : "l"(v));
}

// ---------------------------------------------------------------------------
// K0: copy x0 into g_X rows 0..63 (128KB).
// ---------------------------------------------------------------------------
__global__ void __launch_bounds__(256) k_xcopy(const float* __restrict__ x0)
{
    int i = blockIdx.x * 256 + threadIdx.x;          // 8192 float4s
    ((float4*)g_X)[i] = ((const float4*)x0)[i];
}

// ---------------------------------------------------------------------------
// K1: 128-row tiled drive GEMM (unchanged from R13).
// ---------------------------------------------------------------------------
__global__ void __launch_bounds__(256) k_inp(const float* __restrict__ u,
                                             const float* __restrict__ W_in,
                                             const float* __restrict__ b_in,
                                             const float* __restrict__ noise)
{
    __shared__ __align__(16) float as[64 * 128];
    __shared__ __align__(16) float bs[64 * 64];
    const int bm  = blockIdx.x;
    const int bn  = blockIdx.y;
    const int tid = threadIdx.x;
    const int tx = tid & 15;
    const int ty = tid >> 4;
    const int m0 = bm * 128;
    const int h0 = bn * 64;

#pragma unroll
    for (int s = 0; s < 32; s++) {
        int i = tid + s * 256;
        int r = i >> 6;
        int k = i & 63;
        int sw = (k & 15) << 2;
        int m = m0 + r;
        as[k * 128 + (r ^ sw)] = u[(((size_t)(m & 63) << 10) + (m >> 6)) * 64 + k];
    }
#pragma unroll
    for (int s = 0; s < 16; s++) {
        int i = tid + s * 256;
        int r = i >> 6;
        int k = i & 63;
        int sw = (k & 15) << 2;
        bs[k * 64 + (r ^ sw)] = W_in[(size_t)(h0 + r) * 64 + k];
    }
    __syncthreads();

    ull acc[8][2];
#pragma unroll
    for (int i = 0; i < 8; i++) { acc[i][0] = 0ull; acc[i][1] = 0ull; }

#pragma unroll
    for (int k = 0; k < 64; k++) {
        int sw = (k & 15) << 2;
        float4 a0 = *(const float4*)&as[k * 128 + ((ty * 8) ^ sw)];
        float4 a1 = *(const float4*)&as[k * 128 + (((ty * 8) ^ sw) ^ 4)];
        ulonglong2 w2 = *(const ulonglong2*)&bs[k * 64 + ((tx * 4) ^ sw)];
        ull d0 = dup2(a0.x), d1 = dup2(a0.y), d2 = dup2(a0.z), d3 = dup2(a0.w);
        ull d4 = dup2(a1.x), d5 = dup2(a1.y), d6 = dup2(a1.z), d7 = dup2(a1.w);
        fma2(acc[0][0], d0, w2.x); fma2(acc[0][1], d0, w2.y);
        fma2(acc[1][0], d1, w2.x); fma2(acc[1][1], d1, w2.y);
        fma2(acc[2][0], d2, w2.x); fma2(acc[2][1], d2, w2.y);
        fma2(acc[3][0], d3, w2.x); fma2(acc[3][1], d3, w2.y);
        fma2(acc[4][0], d4, w2.x); fma2(acc[4][1], d4, w2.y);
        fma2(acc[5][0], d5, w2.x); fma2(acc[5][1], d5, w2.y);
        fma2(acc[6][0], d6, w2.x); fma2(acc[6][1], d6, w2.y);
        fma2(acc[7][0], d7, w2.x); fma2(acc[7][1], d7, w2.y);
    }

    const int hc = h0 + tx * 4;
    float4 bias = *(const float4*)&b_in[hc];
#pragma unroll
    for (int i = 0; i < 8; i++) {
        int m = m0 + ty * 8 + i;
        float v0, v1, v2, v3;
        unpack2(acc[i][0], v0, v1);
        unpack2(acc[i][1], v2, v3);
        float4 noi = *(const float4*)&noise[(size_t)m * TH + hc];
        float4 o;
        o.x = fmaf(0.05f, noi.x, 0.2f * (v0 + bias.x));
        o.y = fmaf(0.05f, noi.y, 0.2f * (v1 + bias.y));
        o.z = fmaf(0.05f, noi.z, 0.2f * (v2 + bias.z));
        o.w = fmaf(0.05f, noi.w, 0.2f * (v3 + bias.w));
        *(float4*)&g_drv[(size_t)m * TH + hc] = o;
    }
}

// ---------------------------------------------------------------------------
// K2: chunked elementwise scan, float4 strands (measured 54us / 77% BW).
// ---------------------------------------------------------------------------
__global__ void __launch_bounds__(128) k_scanA(const float* __restrict__ x0)
{
    const int b     = blockIdx.x;
    const int chunk = blockIdx.y;
    const int h4    = threadIdx.x;

    const int t0 = chunk * 64;
    const int tstart = (chunk == 0) ? 0 : t0 - 64;
    const int tend = t0 + 64;

    float4 x;
    if (chunk == 0) x = *(const float4*)&x0[b * TH + 4 * h4];
    else            x = make_float4(0.f, 0.f, 0.f, 0.f);

    const size_t s4 = (size_t)TB * TH / 4;
    const float4* dp = (const float4*)g_drv + (size_t)b * (TH / 4) + h4;
    float4*       xp = (float4*)g_X + (size_t)(TB + b) * (TH / 4) + h4;

    float4 d[8];
#pragma unroll
    for (int p = 0; p < 8; p++)
        d[p] = dp[(size_t)(tstart + p) * s4];

    for (int t = tstart; t < tend; t += 8) {
#pragma unroll
        for (int k = 0; k < 8; k++) {
            x.x = fmaf(0.8f, x.x, d[k].x);
            x.y = fmaf(0.8f, x.y, d[k].y);
            x.z = fmaf(0.8f, x.z, d[k].z);
            x.w = fmaf(0.8f, x.w, d[k].w);
            if (t + k >= t0) xp[(size_t)(t + k) * s4] = x;
            if (t + k + 8 < tend) d[k] = dp[(size_t)(t + k + 8) * s4];
        }
    }
}

// ---------------------------------------------------------------------------
// K3: c1 = tanh(X) @ C tiled GEMM (measured 60us).
// ---------------------------------------------------------------------------
__global__ void __launch_bounds__(128, 6) k_recg(const float* __restrict__ Mw,
                                                 const float* __restrict__ Nw)
{
    __shared__ __align__(16) float xs[64 * 132];
    __shared__ __align__(16) float cs[64 * 16];
    const int tid = threadIdx.x;
    const int tx = tid & 3;
    const int ty = tid >> 2;
    const int row0 = blockIdx.x * 128;

    ull a0[2], a1[2], a2[2], a3[2];
    a0[0] = a0[1] = a1[0] = a1[1] = 0ull;
    a2[0] = a2[1] = a3[0] = a3[1] = 0ull;

    const float* Xbase = g_X + (size_t)row0 * TH;

    for (int kc = 0; kc < 8; kc++) {
        __syncthreads();
#pragma unroll 16
        for (int s = 0; s < 64; s++) {
            int i = tid + s * 128;
            int r = i >> 6;
            int k = i & 63;
            float v = Xbase[(size_t)r * TH + kc * 64 + k];
            xs[k * 132 + r] = fast_tanh(v);
        }
#pragma unroll
        for (int s = 0; s < 8; s++) {
            int i = tid + s * 128;
            int k = i >> 4;
            int d = i & 15;
            int h = kc * 64 + k;
            cs[k * 16 + d] = (d < 8) ? Mw[(size_t)h * TR + d]
                                     : Nw[(size_t)h * TR + (d - 8)];
        }
        __syncthreads();

#pragma unroll
        for (int k = 0; k < 64; k++) {
            float4 a = *(const float4*)&xs[k * 132 + ty * 4];
            ulonglong2 w2 = *(const ulonglong2*)&cs[k * 16 + tx * 4];
            ull d0 = dup2(a.x), d1 = dup2(a.y), d2 = dup2(a.z), d3 = dup2(a.w);
            fma2(a0[0], d0, w2.x); fma2(a0[1], d0, w2.y);
            fma2(a1[0], d1, w2.x); fma2(a1[1], d1, w2.y);
            fma2(a2[0], d2, w2.x); fma2(a2[1], d2, w2.y);
            fma2(a3[0], d3, w2.x); fma2(a3[1], d3, w2.y);
        }
    }

    {
        int m = row0 + ty * 4;
        float v0, v1, v2, v3;
        unpack2(a0[0], v0, v1); unpack2(a0[1], v2, v3);
        *(float4*)&g_c1[(size_t)m * 16 + tx * 4] = make_float4(v0, v1, v2, v3);
        unpack2(a1[0], v0, v1); unpack2(a1[1], v2, v3);
        *(float4*)&g_c1[(size_t)(m + 1) * 16 + tx * 4] = make_float4(v0, v1, v2, v3);
        unpack2(a2[0], v0, v1); unpack2(a2[1], v2, v3);
        *(float4*)&g_c1[(size_t)(m + 2) * 16 + tx * 4] = make_float4(v0, v1, v2, v3);
        unpack2(a3[0], v0, v1); unpack2(a3[1], v2, v3);
        *(float4*)&g_c1[(size_t)(m + 3) * 16 + tx * 4] = make_float4(v0, v1, v2, v3);
    }
}

// ---------------------------------------------------------------------------
// K4: exact parallel weighted scan (measured 11us)
// ---------------------------------------------------------------------------
__global__ void __launch_bounds__(256) k_qscan()
{
    const int b    = blockIdx.x >> 3;
    const int j    = blockIdx.x & 7;
    const int tid  = threadIdx.x;
    const int lane = tid & 31;
    const int wid  = tid >> 5;
    __shared__ float wtot[8];

    const int t0 = tid * 4;
    float p[4];
#pragma unroll
    for (int k = 0; k < 4; k++) {
        size_t base = (size_t)((t0 + k) * TB + b) * 16 + j;
        p[k] = g_c1[base] * g_c1[base + 8];
    }

    float l0 = p[0];
    float l1 = fmaf(0.8f, l0, p[1]);
    float l2 = fmaf(0.8f, l1, p[2]);
    float l3 = fmaf(0.8f, l2, p[3]);

    const float D1 = 0.40960000f;
    float S = l3;
    float dpow = D1;
#pragma unroll
    for (int o = 1; o < 32; o <<= 1) {
        float up = __shfl_up_sync(0xffffffffu, S, o);
        if (lane >= o) S = fmaf(dpow, up, S);
        dpow *= dpow;
    }
    if (lane == 31) wtot[wid] = S;
    __syncthreads();

    const float DW = 4.0173451106474452e-13f;   // 0.8^128
    float W = 0.f, mult = 1.f;
    for (int w = wid - 1; w >= 0; w--) {
        W = fmaf(mult, wtot[w], W);
        mult *= DW;
    }

    float Sx = __shfl_up_sync(0xffffffffu, S, 1);
    if (lane == 0) Sx = 0.f;
    float wdec = 1.f, pb = D1;
    int e = lane;
#pragma unroll
    for (int i = 0; i < 5; i++) {
        if (e & 1) wdec *= pb;
        pb *= pb;
        e >>= 1;
    }
    float E = fmaf(W, wdec, Sx);

    float f = 0.8f * E;
    float* qp = g_q + ((size_t)b * TT + t0) * 8 + j;
    qp[0]  = l0 + f; f *= 0.8f;
    qp[8]  = l1 + f; f *= 0.8f;
    qp[16] = l2 + f; f *= 0.8f;
    qp[24] = l3 + f;
}

// ---------------------------------------------------------------------------
// K5 (FUSED): traj assembly + readout GEMM in one pass.
// Fill stage: tv = x̃[m,h] + KC*(L[h]·q[m]); writes traj (+xlast); tanh into
// smem tile. Key reg economies: per thread k = tid&63 is CONSTANT over the
// fill loop -> L row lives in 8 regs per kc; q row is warp-uniform per s.
// GEMM stage identical to R13 k_out.
// ---------------------------------------------------------------------------
__global__ void __launch_bounds__(256) k_outF(const float* __restrict__ W_out,
                                              const float* __restrict__ b_out,
                                              const float* __restrict__ L,
                                              float* __restrict__ outp,
                                              float* __restrict__ traj,
                                              float* __restrict__ xlast)
{
    __shared__ __align__(16) float at[64 * 128];   // tanh(traj) [k][r^sw] 32KB
    __shared__ __align__(16) float bs2[64 * 64];   // W_out      [k][o^sw] 16KB
    const int bm  = blockIdx.x;                    // 512 blocks x 128 rows
    const int tid = threadIdx.x;
    const int tx = tid & 15;
    const int ty = tid >> 4;
    const int kq = tid & 63;          // fill-k, constant per thread
    const int rb = tid >> 6;          // fill row base (0..3)
    const int swf = (kq & 15) << 2;
    const int m0 = bm * 128;
    const float KC = 0.2f / ((float)TH * (float)TH);

    ull acc[8][2];
#pragma unroll
    for (int i = 0; i < 8; i++) { acc[i][0] = 0ull; acc[i][1] = 0ull; }

    for (int kc = 0; kc < 8; kc++) {
        const int h = kc * 64 + kq;
        const float4 L0 = *(const float4*)(L + (size_t)h * TR);
        const float4 L1 = *(const float4*)(L + (size_t)h * TR + 4);
        __syncthreads();
        // fill at + write traj: 128 rows x 64 k (32 rows per thread slot)
#pragma unroll
        for (int s = 0; s < 32; s++) {
            const int r = rb + s * 4;             // warp-uniform
            const int m = m0 + r;
            const int t = m & (TT - 1);
            const int b = m >> 10;
            // x̃ after step t for batch b lives at g_X row TB + t*TB + b
            float xt = g_X[(size_t)(TB + t * TB + b) * TH + h];
            const float* qp = g_q + (size_t)m * 8; // warp-uniform address
            float4 q0 = *(const float4*)qp;
            float4 q1 = *(const float4*)(qp + 4);
            float e = L0.x * q0.x;
            e = fmaf(L0.y, q0.y, e);
            e = fmaf(L0.z, q0.z, e);
            e = fmaf(L0.w, q0.w, e);
            e = fmaf(L1.x, q1.x, e);
            e = fmaf(L1.y, q1.y, e);
            e = fmaf(L1.z, q1.z, e);
            e = fmaf(L1.w, q1.w, e);
            float tv = fmaf(KC, e, xt);
            traj[(size_t)m * TH + h] = tv;
            if (t == TT - 1) xlast[(size_t)b * TH + h] = tv;
            at[kq * 128 + (r ^ swf)] = acc_tanh(tv);
        }
        // fill bs2: 64 o x 64 k
#pragma unroll
        for (int s = 0; s < 16; s++) {
            int i = tid + s * 256;
            int r = i >> 6;
            int k = i & 63;
            int sw = (k & 15) << 2;
            bs2[k * 64 + (r ^ sw)] = W_out[(size_t)r * TH + kc * 64 + k];
        }
        __syncthreads();
#pragma unroll
        for (int k = 0; k < 64; k++) {
            int swk = (k & 15) << 2;
            float4 a0 = *(const float4*)&at[k * 128 + ((ty * 8) ^ swk)];
            float4 a1 = *(const float4*)&at[k * 128 + (((ty * 8) ^ swk) ^ 4)];
            ulonglong2 w2 = *(const ulonglong2*)&bs2[k * 64 + ((tx * 4) ^ swk)];
            ull d0 = dup2(a0.x), d1 = dup2(a0.y), d2 = dup2(a0.z), d3 = dup2(a0.w);
            ull d4 = dup2(a1.x), d5 = dup2(a1.y), d6 = dup2(a1.z), d7 = dup2(a1.w);
            fma2(acc[0][0], d0, w2.x); fma2(acc[0][1], d0, w2.y);
            fma2(acc[1][0], d1, w2.x); fma2(acc[1][1], d1, w2.y);
            fma2(acc[2][0], d2, w2.x); fma2(acc[2][1], d2, w2.y);
            fma2(acc[3][0], d3, w2.x); fma2(acc[3][1], d3, w2.y);
            fma2(acc[4][0], d4, w2.x); fma2(acc[4][1], d4, w2.y);
            fma2(acc[5][0], d5, w2.x); fma2(acc[5][1], d5, w2.y);
            fma2(acc[6][0], d6, w2.x); fma2(acc[6][1], d6, w2.y);
            fma2(acc[7][0], d7, w2.x); fma2(acc[7][1], d7, w2.y);
        }
    }

    const int o0 = tx * 4;
    float4 bias = *(const float4*)&b_out[o0];
#pragma unroll
    for (int i = 0; i < 8; i++) {
        int m = m0 + ty * 8 + i;
        float v0, v1, v2, v3;
        unpack2(acc[i][0], v0, v1);
        unpack2(acc[i][1], v2, v3);
        float4 o;
        o.x = v0 + bias.x; o.y = v1 + bias.y;
        o.z = v2 + bias.z; o.w = v3 + bias.w;
        *(float4*)&outp[(size_t)m * TO + o0] = o;
    }
}

// ---------------------------------------------------------------------------
// Launcher. Inputs: u, x0, noise, L, M, N, W_in, b_in, W_out, b_out.
// Output: [output | x_last | traj].
// Chain: xcopy(1) -> inp(2) -> scanA(3) -> recg(4, profiled) -> qscan(5)
//        -> outF(6).
// ---------------------------------------------------------------------------
extern "C" void kernel_launch(void* const* d_in, const int* in_sizes, int n_in,
                              void* d_out, int out_size)
{
    (void)in_sizes; (void)n_in; (void)out_size;
    const float* u     = (const float*)d_in[0];
    const float* x0    = (const float*)d_in[1];
    const float* noise = (const float*)d_in[2];
    const float* L     = (const float*)d_in[3];
    const float* Mw    = (const float*)d_in[4];
    const float* Nw    = (const float*)d_in[5];
    const float* W_in  = (const float*)d_in[6];
    const float* b_in  = (const float*)d_in[7];
    const float* W_out = (const float*)d_in[8];
    const float* b_out = (const float*)d_in[9];

    float* outp  = (float*)d_out;
    float* xlast = outp + (size_t)TB * TT * TO;
    float* traj  = xlast + (size_t)TB * TH;

    k_xcopy<<<32, 256>>>(x0);
    k_inp<<<dim3(512, 8), 256>>>(u, W_in, b_in, noise);
    k_scanA<<<dim3(64, 16), 128>>>(x0);
    k_recg<<<512, 128>>>(Mw, Nw);
    k_qscan<<<512, 256>>>();
    k_outF<<<(TB * TT) / 128, 256>>>(W_out, b_out, L, outp, traj, xlast);
}

// round 15
// speedup vs baseline: 1.5581x; 1.5581x over previous
#include <cuda_runtime.h>
#include <cstddef>

#define TB 64
#define TT 1024
#define TI 64
#define TH 512
#define TR 8
#define TO 64

typedef unsigned long long ull;

// combined drive d = 0.05*noise + 0.2*(u@W_in^T + b_in), layout [T,B,H]
__device__ float g_drv[(size_t)TT * TB * TH];
// unified state buffer: rows 0..63 = x0; row 64+(t*B+b) = x̃ after step t
__device__ float g_X[((size_t)TT * TB + TB) * TH];
// 16 dots at state BEFORE step t, row m=t*B+b: g_c1[m*16+d]; d<8: r@M, d>=8: r@N
__device__ float g_c1[(size_t)TT * TB * 16];
// scanned products: g_q[(b*T+t)*8 + j]
__device__ float g_q[(size_t)TB * TT * 8];

__device__ __forceinline__ float fast_tanh(float x) {
    float y;
    asm("tanh.approx.f32 %0, %1;" : "=f"(y) : "f"(x));
    return y;
}
__device__ __forceinline__ float acc_tanh(float x) {
    float e;
    asm("ex2.approx.f32 %0, %1;" : "=f"(e) : "f"(x * 2.8853900817779268f));
    float d;
    asm("rcp.approx.f32 %0, %1;" : "=f"(d) : "f"(e + 1.0f));
    return fmaf(-2.0f, d, 1.0f);
}
__device__ __forceinline__ void fma2(ull& acc, ull a, ull b) {
    asm("fma.rn.f32x2 %0, %1, %2, %0;" : "+l"(acc) : "l"(a), "l"(b));
}
__device__ __forceinline__ ull dup2(float a) {
    ull d;
    asm("mov.b64 %0, {%1, %1};" : "=l"(d) : "f"(a));
    return d;
}
__device__ __forceinline__ void unpack2(ull v, float& lo, float& hi) {
    asm("mov.b64 {%0, %1}, %2;" : "=f"(lo), "=f"(hi) : "l"(v));
}

// ---------------------------------------------------------------------------
// K0: copy x0 into g_X rows 0..63 (128KB).
// ---------------------------------------------------------------------------
__global__ void __launch_bounds__(256) k_xcopy(const float* __restrict__ x0)
{
    int i = blockIdx.x * 256 + threadIdx.x;          // 8192 float4s
    ((float4*)g_X)[i] = ((const float4*)x0)[i];
}

// ---------------------------------------------------------------------------
// K1: 128-row tiled drive GEMM (R13, measured-good).
// ---------------------------------------------------------------------------
__global__ void __launch_bounds__(256) k_inp(const float* __restrict__ u,
                                             const float* __restrict__ W_in,
                                             const float* __restrict__ b_in,
                                             const float* __restrict__ noise)
{
    __shared__ __align__(16) float as[64 * 128];
    __shared__ __align__(16) float bs[64 * 64];
    const int bm  = blockIdx.x;
    const int bn  = blockIdx.y;
    const int tid = threadIdx.x;
    const int tx = tid & 15;
    const int ty = tid >> 4;
    const int m0 = bm * 128;
    const int h0 = bn * 64;

#pragma unroll
    for (int s = 0; s < 32; s++) {
        int i = tid + s * 256;
        int r = i >> 6;
        int k = i & 63;
        int sw = (k & 15) << 2;
        int m = m0 + r;
        as[k * 128 + (r ^ sw)] = u[(((size_t)(m & 63) << 10) + (m >> 6)) * 64 + k];
    }
#pragma unroll
    for (int s = 0; s < 16; s++) {
        int i = tid + s * 256;
        int r = i >> 6;
        int k = i & 63;
        int sw = (k & 15) << 2;
        bs[k * 64 + (r ^ sw)] = W_in[(size_t)(h0 + r) * 64 + k];
    }
    __syncthreads();

    ull acc[8][2];
#pragma unroll
    for (int i = 0; i < 8; i++) { acc[i][0] = 0ull; acc[i][1] = 0ull; }

#pragma unroll
    for (int k = 0; k < 64; k++) {
        int sw = (k & 15) << 2;
        float4 a0 = *(const float4*)&as[k * 128 + ((ty * 8) ^ sw)];
        float4 a1 = *(const float4*)&as[k * 128 + (((ty * 8) ^ sw) ^ 4)];
        ulonglong2 w2 = *(const ulonglong2*)&bs[k * 64 + ((tx * 4) ^ sw)];
        ull d0 = dup2(a0.x), d1 = dup2(a0.y), d2 = dup2(a0.z), d3 = dup2(a0.w);
        ull d4 = dup2(a1.x), d5 = dup2(a1.y), d6 = dup2(a1.z), d7 = dup2(a1.w);
        fma2(acc[0][0], d0, w2.x); fma2(acc[0][1], d0, w2.y);
        fma2(acc[1][0], d1, w2.x); fma2(acc[1][1], d1, w2.y);
        fma2(acc[2][0], d2, w2.x); fma2(acc[2][1], d2, w2.y);
        fma2(acc[3][0], d3, w2.x); fma2(acc[3][1], d3, w2.y);
        fma2(acc[4][0], d4, w2.x); fma2(acc[4][1], d4, w2.y);
        fma2(acc[5][0], d5, w2.x); fma2(acc[5][1], d5, w2.y);
        fma2(acc[6][0], d6, w2.x); fma2(acc[6][1], d6, w2.y);
        fma2(acc[7][0], d7, w2.x); fma2(acc[7][1], d7, w2.y);
    }

    const int hc = h0 + tx * 4;
    float4 bias = *(const float4*)&b_in[hc];
#pragma unroll
    for (int i = 0; i < 8; i++) {
        int m = m0 + ty * 8 + i;
        float v0, v1, v2, v3;
        unpack2(acc[i][0], v0, v1);
        unpack2(acc[i][1], v2, v3);
        float4 noi = *(const float4*)&noise[(size_t)m * TH + hc];
        float4 o;
        o.x = fmaf(0.05f, noi.x, 0.2f * (v0 + bias.x));
        o.y = fmaf(0.05f, noi.y, 0.2f * (v1 + bias.y));
        o.z = fmaf(0.05f, noi.z, 0.2f * (v2 + bias.z));
        o.w = fmaf(0.05f, noi.w, 0.2f * (v3 + bias.w));
        *(float4*)&g_drv[(size_t)m * TH + hc] = o;
    }
}

// ---------------------------------------------------------------------------
// K2: chunked elementwise scan, float4 strands (measured 54us / 77% BW).
// ---------------------------------------------------------------------------
__global__ void __launch_bounds__(128) k_scanA(const float* __restrict__ x0)
{
    const int b     = blockIdx.x;
    const int chunk = blockIdx.y;
    const int h4    = threadIdx.x;

    const int t0 = chunk * 64;
    const int tstart = (chunk == 0) ? 0 : t0 - 64;
    const int tend = t0 + 64;

    float4 x;
    if (chunk == 0) x = *(const float4*)&x0[b * TH + 4 * h4];
    else            x = make_float4(0.f, 0.f, 0.f, 0.f);

    const size_t s4 = (size_t)TB * TH / 4;
    const float4* dp = (const float4*)g_drv + (size_t)b * (TH / 4) + h4;
    float4*       xp = (float4*)g_X + (size_t)(TB + b) * (TH / 4) + h4;

    float4 d[8];
#pragma unroll
    for (int p = 0; p < 8; p++)
        d[p] = dp[(size_t)(tstart + p) * s4];

    for (int t = tstart; t < tend; t += 8) {
#pragma unroll
        for (int k = 0; k < 8; k++) {
            x.x = fmaf(0.8f, x.x, d[k].x);
            x.y = fmaf(0.8f, x.y, d[k].y);
            x.z = fmaf(0.8f, x.z, d[k].z);
            x.w = fmaf(0.8f, x.w, d[k].w);
            if (t + k >= t0) xp[(size_t)(t + k) * s4] = x;
            if (t + k + 8 < tend) d[k] = dp[(size_t)(t + k + 8) * s4];
        }
    }
}

// ---------------------------------------------------------------------------
// K3: c1 = tanh(X) @ C tiled GEMM. CHANGE vs R13: xor-swizzle on the x-tile
// (fill stores r^sw, compute reads (ty*4)^sw) to kill 4-way STS bank
// conflicts flagged by L1=63.6% in the R13/R14 profiles.
// ---------------------------------------------------------------------------
__global__ void __launch_bounds__(128, 6) k_recg(const float* __restrict__ Mw,
                                                 const float* __restrict__ Nw)
{
    __shared__ __align__(16) float xs[64 * 132];   // [k][r^sw], pad-132
    __shared__ __align__(16) float cs[64 * 16];    // C slice [k][d]
    const int tid = threadIdx.x;
    const int tx = tid & 3;          // col group (4 cols)
    const int ty = tid >> 2;         // 32 row groups (4 rows each)
    const int row0 = blockIdx.x * 128;

    ull a0[2], a1[2], a2[2], a3[2];
    a0[0] = a0[1] = a1[0] = a1[1] = 0ull;
    a2[0] = a2[1] = a3[0] = a3[1] = 0ull;

    const float* Xbase = g_X + (size_t)row0 * TH;

    for (int kc = 0; kc < 8; kc++) {
        __syncthreads();
        // fill x tile: 128 rows x 64 k (64 elems/thread), swizzled store
#pragma unroll 16
        for (int s = 0; s < 64; s++) {
            int i = tid + s * 128;
            int r = i >> 6;          // 0..127
            int k = i & 63;
            int sw = (k & 15) << 2;
            float v = Xbase[(size_t)r * TH + kc * 64 + k];
            xs[k * 132 + (r ^ sw)] = fast_tanh(v);
        }
        // fill C slice: 64 k x 16 d (8 elems/thread)
#pragma unroll
        for (int s = 0; s < 8; s++) {
            int i = tid + s * 128;
            int k = i >> 4;          // 0..63
            int d = i & 15;
            int h = kc * 64 + k;
            cs[k * 16 + d] = (d < 8) ? Mw[(size_t)h * TR + d]
                                     : Nw[(size_t)h * TR + (d - 8)];
        }
        __syncthreads();

#pragma unroll
        for (int k = 0; k < 64; k++) {
            int sw = (k & 15) << 2;
            float4 a = *(const float4*)&xs[k * 132 + ((ty * 4) ^ sw)];
            ulonglong2 w2 = *(const ulonglong2*)&cs[k * 16 + tx * 4];
            ull d0 = dup2(a.x), d1 = dup2(a.y), d2 = dup2(a.z), d3 = dup2(a.w);
            fma2(a0[0], d0, w2.x); fma2(a0[1], d0, w2.y);
            fma2(a1[0], d1, w2.x); fma2(a1[1], d1, w2.y);
            fma2(a2[0], d2, w2.x); fma2(a2[1], d2, w2.y);
            fma2(a3[0], d3, w2.x); fma2(a3[1], d3, w2.y);
        }
    }

    {
        int m = row0 + ty * 4;
        float v0, v1, v2, v3;
        unpack2(a0[0], v0, v1); unpack2(a0[1], v2, v3);
        *(float4*)&g_c1[(size_t)m * 16 + tx * 4] = make_float4(v0, v1, v2, v3);
        unpack2(a1[0], v0, v1); unpack2(a1[1], v2, v3);
        *(float4*)&g_c1[(size_t)(m + 1) * 16 + tx * 4] = make_float4(v0, v1, v2, v3);
        unpack2(a2[0], v0, v1); unpack2(a2[1], v2, v3);
        *(float4*)&g_c1[(size_t)(m + 2) * 16 + tx * 4] = make_float4(v0, v1, v2, v3);
        unpack2(a3[0], v0, v1); unpack2(a3[1], v2, v3);
        *(float4*)&g_c1[(size_t)(m + 3) * 16 + tx * 4] = make_float4(v0, v1, v2, v3);
    }
}

// ---------------------------------------------------------------------------
// K4: exact parallel weighted scan (measured 11us)
// ---------------------------------------------------------------------------
__global__ void __launch_bounds__(256) k_qscan()
{
    const int b    = blockIdx.x >> 3;
    const int j    = blockIdx.x & 7;
    const int tid  = threadIdx.x;
    const int lane = tid & 31;
    const int wid  = tid >> 5;
    __shared__ float wtot[8];

    const int t0 = tid * 4;
    float p[4];
#pragma unroll
    for (int k = 0; k < 4; k++) {
        size_t base = (size_t)((t0 + k) * TB + b) * 16 + j;
        p[k] = g_c1[base] * g_c1[base + 8];
    }

    float l0 = p[0];
    float l1 = fmaf(0.8f, l0, p[1]);
    float l2 = fmaf(0.8f, l1, p[2]);
    float l3 = fmaf(0.8f, l2, p[3]);

    const float D1 = 0.40960000f;
    float S = l3;
    float dpow = D1;
#pragma unroll
    for (int o = 1; o < 32; o <<= 1) {
        float up = __shfl_up_sync(0xffffffffu, S, o);
        if (lane >= o) S = fmaf(dpow, up, S);
        dpow *= dpow;
    }
    if (lane == 31) wtot[wid] = S;
    __syncthreads();

    const float DW = 4.0173451106474452e-13f;   // 0.8^128
    float W = 0.f, mult = 1.f;
    for (int w = wid - 1; w >= 0; w--) {
        W = fmaf(mult, wtot[w], W);
        mult *= DW;
    }

    float Sx = __shfl_up_sync(0xffffffffu, S, 1);
    if (lane == 0) Sx = 0.f;
    float wdec = 1.f, pb = D1;
    int e = lane;
#pragma unroll
    for (int i = 0; i < 5; i++) {
        if (e & 1) wdec *= pb;
        pb *= pb;
        e >>= 1;
    }
    float E = fmaf(W, wdec, Sx);

    float f = 0.8f * E;
    float* qp = g_q + ((size_t)b * TT + t0) * 8 + j;
    qp[0]  = l0 + f; f *= 0.8f;
    qp[8]  = l1 + f; f *= 0.8f;
    qp[16] = l2 + f; f *= 0.8f;
    qp[24] = l3 + f;
}

// ---------------------------------------------------------------------------
// K5: streaming traj assembly (R13 version, ~95us)
// ---------------------------------------------------------------------------
__global__ void __launch_bounds__(128) k_trajA(const float* __restrict__ L,
                                               float* __restrict__ traj,
                                               float* __restrict__ xlast)
{
    const int b     = blockIdx.x;
    const int chunk = blockIdx.y;
    const int h4    = threadIdx.x;
    const float KC = 0.2f / ((float)TH * (float)TH);

    float4 La[4], Lb[4];
#pragma unroll
    for (int i = 0; i < 4; i++) {
        La[i] = *(const float4*)(L + (size_t)(4 * h4 + i) * TR);
        Lb[i] = *(const float4*)(L + (size_t)(4 * h4 + i) * TR + 4);
    }

    const int t0 = chunk * 64;
    const int tend = t0 + 64;

    const size_t s4 = (size_t)TB * TH / 4;
    const float4* xp = (const float4*)g_X + (size_t)(TB + b) * (TH / 4) + h4;
    float4* tp = (float4*)traj + ((size_t)b * TT) * (TH / 4) + h4;
    const float* qbase = g_q + ((size_t)b * TT) * 8;

    float4 xr[8];
#pragma unroll
    for (int p = 0; p < 8; p++)
        xr[p] = xp[(size_t)(t0 + p) * s4];

    for (int t = t0; t < tend; t += 8) {
#pragma unroll
        for (int k = 0; k < 8; k++) {
            const int tt = t + k;
            float4 q0 = *(const float4*)(qbase + (size_t)tt * 8);
            float4 q1 = *(const float4*)(qbase + (size_t)tt * 8 + 4);

            float4 xt = xr[k];
            float4 tv;
            float e0 = La[0].x * q0.x;
            e0 = fmaf(La[0].y, q0.y, e0); e0 = fmaf(La[0].z, q0.z, e0);
            e0 = fmaf(La[0].w, q0.w, e0); e0 = fmaf(Lb[0].x, q1.x, e0);
            e0 = fmaf(Lb[0].y, q1.y, e0); e0 = fmaf(Lb[0].z, q1.z, e0);
            e0 = fmaf(Lb[0].w, q1.w, e0);
            tv.x = fmaf(KC, e0, xt.x);
            float e1 = La[1].x * q0.x;
            e1 = fmaf(La[1].y, q0.y, e1); e1 = fmaf(La[1].z, q0.z, e1);
            e1 = fmaf(La[1].w, q0.w, e1); e1 = fmaf(Lb[1].x, q1.x, e1);
            e1 = fmaf(Lb[1].y, q1.y, e1); e1 = fmaf(Lb[1].z, q1.z, e1);
            e1 = fmaf(Lb[1].w, q1.w, e1);
            tv.y = fmaf(KC, e1, xt.y);
            float e2 = La[2].x * q0.x;
            e2 = fmaf(La[2].y, q0.y, e2); e2 = fmaf(La[2].z, q0.z, e2);
            e2 = fmaf(La[2].w, q0.w, e2); e2 = fmaf(Lb[2].x, q1.x, e2);
            e2 = fmaf(Lb[2].y, q1.y, e2); e2 = fmaf(Lb[2].z, q1.z, e2);
            e2 = fmaf(Lb[2].w, q1.w, e2);
            tv.z = fmaf(KC, e2, xt.z);
            float e3 = La[3].x * q0.x;
            e3 = fmaf(La[3].y, q0.y, e3); e3 = fmaf(La[3].z, q0.z, e3);
            e3 = fmaf(La[3].w, q0.w, e3); e3 = fmaf(Lb[3].x, q1.x, e3);
            e3 = fmaf(Lb[3].y, q1.y, e3); e3 = fmaf(Lb[3].z, q1.z, e3);
            e3 = fmaf(Lb[3].w, q1.w, e3);
            tv.w = fmaf(KC, e3, xt.w);

            tp[(size_t)tt * (TH / 4)] = tv;
            if (tt == TT - 1)
                *((float4*)xlast + (size_t)b * (TH / 4) + h4) = tv;
            if (tt + 8 < tend) xr[k] = xp[(size_t)(tt + 8) * s4];
        }
    }
}

// ---------------------------------------------------------------------------
// K6: readout GEMM, 128-row tiles (R13 version, ~140us)
// ---------------------------------------------------------------------------
__global__ void __launch_bounds__(256) k_out(const float* __restrict__ traj,
                                             const float* __restrict__ W_out,
                                             const float* __restrict__ b_out,
                                             float* __restrict__ outp)
{
    __shared__ __align__(16) float at[64 * 128];
    __shared__ __align__(16) float bs2[64 * 64];
    const int bm  = blockIdx.x;
    const int tid = threadIdx.x;
    const int tx = tid & 15;
    const int ty = tid >> 4;

    ull acc[8][2];
#pragma unroll
    for (int i = 0; i < 8; i++) { acc[i][0] = 0ull; acc[i][1] = 0ull; }

    for (int kc = 0; kc < 8; kc++) {
        __syncthreads();
#pragma unroll
        for (int s = 0; s < 32; s++) {
            int i = tid + s * 256;
            int r = i >> 6;
            int k = i & 63;
            int sw = (k & 15) << 2;
            float tv = traj[((size_t)(bm * 128 + r)) * TH + kc * 64 + k];
            at[k * 128 + (r ^ sw)] = acc_tanh(tv);
        }
#pragma unroll
        for (int s = 0; s < 16; s++) {
            int i = tid + s * 256;
            int r = i >> 6;
            int k = i & 63;
            int sw = (k & 15) << 2;
            bs2[k * 64 + (r ^ sw)] = W_out[(size_t)r * TH + kc * 64 + k];
        }
        __syncthreads();
#pragma unroll
        for (int k = 0; k < 64; k++) {
            int swk = (k & 15) << 2;
            float4 a0 = *(const float4*)&at[k * 128 + ((ty * 8) ^ swk)];
            float4 a1 = *(const float4*)&at[k * 128 + (((ty * 8) ^ swk) ^ 4)];
            ulonglong2 w2 = *(const ulonglong2*)&bs2[k * 64 + ((tx * 4) ^ swk)];
            ull d0 = dup2(a0.x), d1 = dup2(a0.y), d2 = dup2(a0.z), d3 = dup2(a0.w);
            ull d4 = dup2(a1.x), d5 = dup2(a1.y), d6 = dup2(a1.z), d7 = dup2(a1.w);
            fma2(acc[0][0], d0, w2.x); fma2(acc[0][1], d0, w2.y);
            fma2(acc[1][0], d1, w2.x); fma2(acc[1][1], d1, w2.y);
            fma2(acc[2][0], d2, w2.x); fma2(acc[2][1], d2, w2.y);
            fma2(acc[3][0], d3, w2.x); fma2(acc[3][1], d3, w2.y);
            fma2(acc[4][0], d4, w2.x); fma2(acc[4][1], d4, w2.y);
            fma2(acc[5][0], d5, w2.x); fma2(acc[5][1], d5, w2.y);
            fma2(acc[6][0], d6, w2.x); fma2(acc[6][1], d6, w2.y);
            fma2(acc[7][0], d7, w2.x); fma2(acc[7][1], d7, w2.y);
        }
    }

    const int o0 = tx * 4;
    float4 bias = *(const float4*)&b_out[o0];
#pragma unroll
    for (int i = 0; i < 8; i++) {
        int m = bm * 128 + ty * 8 + i;
        float v0, v1, v2, v3;
        unpack2(acc[i][0], v0, v1);
        unpack2(acc[i][1], v2, v3);
        float4 o;
        o.x = v0 + bias.x; o.y = v1 + bias.y;
        o.z = v2 + bias.z; o.w = v3 + bias.w;
        *(float4*)&outp[(size_t)m * TO + o0] = o;
    }
}

// ---------------------------------------------------------------------------
// Launcher. Inputs: u, x0, noise, L, M, N, W_in, b_in, W_out, b_out.
// Output: [output | x_last | traj].
// Chain: xcopy(1) -> inp(2) -> scanA(3) -> recg(4, profiled) -> qscan(5)
//        -> trajA(6) -> out(7).
// ---------------------------------------------------------------------------
extern "C" void kernel_launch(void* const* d_in, const int* in_sizes, int n_in,
                              void* d_out, int out_size)
{
    (void)in_sizes; (void)n_in; (void)out_size;
    const float* u     = (const float*)d_in[0];
    const float* x0    = (const float*)d_in[1];
    const float* noise = (const float*)d_in[2];
    const float* L     = (const float*)d_in[3];
    const float* Mw    = (const float*)d_in[4];
    const float* Nw    = (const float*)d_in[5];
    const float* W_in  = (const float*)d_in[6];
    const float* b_in  = (const float*)d_in[7];
    const float* W_out = (const float*)d_in[8];
    const float* b_out = (const float*)d_in[9];

    float* outp  = (float*)d_out;
    float* xlast = outp + (size_t)TB * TT * TO;
    float* traj  = xlast + (size_t)TB * TH;

    k_xcopy<<<32, 256>>>(x0);
    k_inp<<<dim3(512, 8), 256>>>(u, W_in, b_in, noise);
    k_scanA<<<dim3(64, 16), 128>>>(x0);
    k_recg<<<512, 128>>>(Mw, Nw);
    k_qscan<<<512, 256>>>();
    k_trajA<<<dim3(64, 16), 128>>>(L, traj, xlast);
    k_out<<<(TB * TT) / 128, 256>>>(traj, W_out, b_out, outp);
}

// round 16
// speedup vs baseline: 1.7633x; 1.1316x over previous
#include <cuda_runtime.h>
#include <cstddef>

#define TB 64
#define TT 1024
#define TI 64
#define TH 512
#define TR 8
#define TO 64

typedef unsigned long long ull;

// combined drive d = 0.05*noise + 0.2*(u@W_in^T + b_in), layout [T,B,H]
__device__ float g_drv[(size_t)TT * TB * TH];
// unified state buffer: rows 0..63 = x0; row 64+(t*B+b) = x̃ after step t
__device__ float g_X[((size_t)TT * TB + TB) * TH];
// 16 dots at state BEFORE step t, row m=t*B+b: g_c1[m*16+d]; d<8: r@M, d>=8: r@N
__device__ float g_c1[(size_t)TT * TB * 16];
// scanned products: g_q[(b*T+t)*8 + j]
__device__ float g_q[(size_t)TB * TT * 8];

__device__ __forceinline__ float fast_tanh(float x) {
    float y;
    asm("tanh.approx.f32 %0, %1;" : "=f"(y) : "f"(x));
    return y;
}
__device__ __forceinline__ float acc_tanh(float x) {
    float e;
    asm("ex2.approx.f32 %0, %1;" : "=f"(e) : "f"(x * 2.8853900817779268f));
    float d;
    asm("rcp.approx.f32 %0, %1;" : "=f"(d) : "f"(e + 1.0f));
    return fmaf(-2.0f, d, 1.0f);
}
__device__ __forceinline__ void fma2(ull& acc, ull a, ull b) {
    asm("fma.rn.f32x2 %0, %1, %2, %0;" : "+l"(acc) : "l"(a), "l"(b));
}
__device__ __forceinline__ ull dup2(float a) {
    ull d;
    asm("mov.b64 %0, {%1, %1};" : "=l"(d) : "f"(a));
    return d;
}
__device__ __forceinline__ void unpack2(ull v, float& lo, float& hi) {
    asm("mov.b64 {%0, %1}, %2;" : "=f"(lo), "=f"(hi) : "l"(v));
}

// ---------------------------------------------------------------------------
// K0: copy x0 into g_X rows 0..63 (128KB).
// ---------------------------------------------------------------------------
__global__ void __launch_bounds__(256) k_xcopy(const float* __restrict__ x0)
{
    int i = blockIdx.x * 256 + threadIdx.x;          // 8192 float4s
    ((float4*)g_X)[i] = ((const float4*)x0)[i];
}

// ---------------------------------------------------------------------------
// K1: 128-row tiled drive GEMM (R13, measured-good).
// ---------------------------------------------------------------------------
__global__ void __launch_bounds__(256) k_inp(const float* __restrict__ u,
                                             const float* __restrict__ W_in,
                                             const float* __restrict__ b_in,
                                             const float* __restrict__ noise)
{
    __shared__ __align__(16) float as[64 * 128];
    __shared__ __align__(16) float bs[64 * 64];
    const int bm  = blockIdx.x;
    const int bn  = blockIdx.y;
    const int tid = threadIdx.x;
    const int tx = tid & 15;
    const int ty = tid >> 4;
    const int m0 = bm * 128;
    const int h0 = bn * 64;

#pragma unroll
    for (int s = 0; s < 32; s++) {
        int i = tid + s * 256;
        int r = i >> 6;
        int k = i & 63;
        int sw = (k & 15) << 2;
        int m = m0 + r;
        as[k * 128 + (r ^ sw)] = u[(((size_t)(m & 63) << 10) + (m >> 6)) * 64 + k];
    }
#pragma unroll
    for (int s = 0; s < 16; s++) {
        int i = tid + s * 256;
        int r = i >> 6;
        int k = i & 63;
        int sw = (k & 15) << 2;
        bs[k * 64 + (r ^ sw)] = W_in[(size_t)(h0 + r) * 64 + k];
    }
    __syncthreads();

    ull acc[8][2];
#pragma unroll
    for (int i = 0; i < 8; i++) { acc[i][0] = 0ull; acc[i][1] = 0ull; }

#pragma unroll
    for (int k = 0; k < 64; k++) {
        int sw = (k & 15) << 2;
        float4 a0 = *(const float4*)&as[k * 128 + ((ty * 8) ^ sw)];
        float4 a1 = *(const float4*)&as[k * 128 + (((ty * 8) ^ sw) ^ 4)];
        ulonglong2 w2 = *(const ulonglong2*)&bs[k * 64 + ((tx * 4) ^ sw)];
        ull d0 = dup2(a0.x), d1 = dup2(a0.y), d2 = dup2(a0.z), d3 = dup2(a0.w);
        ull d4 = dup2(a1.x), d5 = dup2(a1.y), d6 = dup2(a1.z), d7 = dup2(a1.w);
        fma2(acc[0][0], d0, w2.x); fma2(acc[0][1], d0, w2.y);
        fma2(acc[1][0], d1, w2.x); fma2(acc[1][1], d1, w2.y);
        fma2(acc[2][0], d2, w2.x); fma2(acc[2][1], d2, w2.y);
        fma2(acc[3][0], d3, w2.x); fma2(acc[3][1], d3, w2.y);
        fma2(acc[4][0], d4, w2.x); fma2(acc[4][1], d4, w2.y);
        fma2(acc[5][0], d5, w2.x); fma2(acc[5][1], d5, w2.y);
        fma2(acc[6][0], d6, w2.x); fma2(acc[6][1], d6, w2.y);
        fma2(acc[7][0], d7, w2.x); fma2(acc[7][1], d7, w2.y);
    }

    const int hc = h0 + tx * 4;
    float4 bias = *(const float4*)&b_in[hc];
#pragma unroll
    for (int i = 0; i < 8; i++) {
        int m = m0 + ty * 8 + i;
        float v0, v1, v2, v3;
        unpack2(acc[i][0], v0, v1);
        unpack2(acc[i][1], v2, v3);
        float4 noi = *(const float4*)&noise[(size_t)m * TH + hc];
        float4 o;
        o.x = fmaf(0.05f, noi.x, 0.2f * (v0 + bias.x));
        o.y = fmaf(0.05f, noi.y, 0.2f * (v1 + bias.y));
        o.z = fmaf(0.05f, noi.z, 0.2f * (v2 + bias.z));
        o.w = fmaf(0.05f, noi.w, 0.2f * (v3 + bias.w));
        *(float4*)&g_drv[(size_t)m * TH + hc] = o;
    }
}

// ---------------------------------------------------------------------------
// K2: chunked elementwise scan, float4 strands (measured 54us / 77% BW).
// ---------------------------------------------------------------------------
__global__ void __launch_bounds__(128) k_scanA(const float* __restrict__ x0)
{
    const int b     = blockIdx.x;
    const int chunk = blockIdx.y;
    const int h4    = threadIdx.x;

    const int t0 = chunk * 64;
    const int tstart = (chunk == 0) ? 0 : t0 - 64;
    const int tend = t0 + 64;

    float4 x;
    if (chunk == 0) x = *(const float4*)&x0[b * TH + 4 * h4];
    else            x = make_float4(0.f, 0.f, 0.f, 0.f);

    const size_t s4 = (size_t)TB * TH / 4;
    const float4* dp = (const float4*)g_drv + (size_t)b * (TH / 4) + h4;
    float4*       xp = (float4*)g_X + (size_t)(TB + b) * (TH / 4) + h4;

    float4 d[8];
#pragma unroll
    for (int p = 0; p < 8; p++)
        d[p] = dp[(size_t)(tstart + p) * s4];

    for (int t = tstart; t < tend; t += 8) {
#pragma unroll
        for (int k = 0; k < 8; k++) {
            x.x = fmaf(0.8f, x.x, d[k].x);
            x.y = fmaf(0.8f, x.y, d[k].y);
            x.z = fmaf(0.8f, x.z, d[k].z);
            x.w = fmaf(0.8f, x.w, d[k].w);
            if (t + k >= t0) xp[(size_t)(t + k) * s4] = x;
            if (t + k + 8 < tend) d[k] = dp[(size_t)(t + k + 8) * s4];
        }
    }
}

// ---------------------------------------------------------------------------
// K3: c1 = tanh(X) @ C tiled GEMM (R13 exact, measured 60us — swizzle REVERTED)
// ---------------------------------------------------------------------------
__global__ void __launch_bounds__(128, 6) k_recg(const float* __restrict__ Mw,
                                                 const float* __restrict__ Nw)
{
    __shared__ __align__(16) float xs[64 * 132];
    __shared__ __align__(16) float cs[64 * 16];
    const int tid = threadIdx.x;
    const int tx = tid & 3;
    const int ty = tid >> 2;
    const int row0 = blockIdx.x * 128;

    ull a0[2], a1[2], a2[2], a3[2];
    a0[0] = a0[1] = a1[0] = a1[1] = 0ull;
    a2[0] = a2[1] = a3[0] = a3[1] = 0ull;

    const float* Xbase = g_X + (size_t)row0 * TH;

    for (int kc = 0; kc < 8; kc++) {
        __syncthreads();
#pragma unroll 16
        for (int s = 0; s < 64; s++) {
            int i = tid + s * 128;
            int r = i >> 6;
            int k = i & 63;
            float v = Xbase[(size_t)r * TH + kc * 64 + k];
            xs[k * 132 + r] = fast_tanh(v);
        }
#pragma unroll
        for (int s = 0; s < 8; s++) {
            int i = tid + s * 128;
            int k = i >> 4;
            int d = i & 15;
            int h = kc * 64 + k;
            cs[k * 16 + d] = (d < 8) ? Mw[(size_t)h * TR + d]
                                     : Nw[(size_t)h * TR + (d - 8)];
        }
        __syncthreads();

#pragma unroll
        for (int k = 0; k < 64; k++) {
            float4 a = *(const float4*)&xs[k * 132 + ty * 4];
            ulonglong2 w2 = *(const ulonglong2*)&cs[k * 16 + tx * 4];
            ull d0 = dup2(a.x), d1 = dup2(a.y), d2 = dup2(a.z), d3 = dup2(a.w);
            fma2(a0[0], d0, w2.x); fma2(a0[1], d0, w2.y);
            fma2(a1[0], d1, w2.x); fma2(a1[1], d1, w2.y);
            fma2(a2[0], d2, w2.x); fma2(a2[1], d2, w2.y);
            fma2(a3[0], d3, w2.x); fma2(a3[1], d3, w2.y);
        }
    }

    {
        int m = row0 + ty * 4;
        float v0, v1, v2, v3;
        unpack2(a0[0], v0, v1); unpack2(a0[1], v2, v3);
        *(float4*)&g_c1[(size_t)m * 16 + tx * 4] = make_float4(v0, v1, v2, v3);
        unpack2(a1[0], v0, v1); unpack2(a1[1], v2, v3);
        *(float4*)&g_c1[(size_t)(m + 1) * 16 + tx * 4] = make_float4(v0, v1, v2, v3);
        unpack2(a2[0], v0, v1); unpack2(a2[1], v2, v3);
        *(float4*)&g_c1[(size_t)(m + 2) * 16 + tx * 4] = make_float4(v0, v1, v2, v3);
        unpack2(a3[0], v0, v1); unpack2(a3[1], v2, v3);
        *(float4*)&g_c1[(size_t)(m + 3) * 16 + tx * 4] = make_float4(v0, v1, v2, v3);
    }
}

// ---------------------------------------------------------------------------
// K4: exact parallel weighted scan (measured 11us)
// ---------------------------------------------------------------------------
__global__ void __launch_bounds__(256) k_qscan()
{
    const int b    = blockIdx.x >> 3;
    const int j    = blockIdx.x & 7;
    const int tid  = threadIdx.x;
    const int lane = tid & 31;
    const int wid  = tid >> 5;
    __shared__ float wtot[8];

    const int t0 = tid * 4;
    float p[4];
#pragma unroll
    for (int k = 0; k < 4; k++) {
        size_t base = (size_t)((t0 + k) * TB + b) * 16 + j;
        p[k] = g_c1[base] * g_c1[base + 8];
    }

    float l0 = p[0];
    float l1 = fmaf(0.8f, l0, p[1]);
    float l2 = fmaf(0.8f, l1, p[2]);
    float l3 = fmaf(0.8f, l2, p[3]);

    const float D1 = 0.40960000f;
    float S = l3;
    float dpow = D1;
#pragma unroll
    for (int o = 1; o < 32; o <<= 1) {
        float up = __shfl_up_sync(0xffffffffu, S, o);
        if (lane >= o) S = fmaf(dpow, up, S);
        dpow *= dpow;
    }
    if (lane == 31) wtot[wid] = S;
    __syncthreads();

    const float DW = 4.0173451106474452e-13f;   // 0.8^128
    float W = 0.f, mult = 1.f;
    for (int w = wid - 1; w >= 0; w--) {
        W = fmaf(mult, wtot[w], W);
        mult *= DW;
    }

    float Sx = __shfl_up_sync(0xffffffffu, S, 1);
    if (lane == 0) Sx = 0.f;
    float wdec = 1.f, pb = D1;
    int e = lane;
#pragma unroll
    for (int i = 0; i < 5; i++) {
        if (e & 1) wdec *= pb;
        pb *= pb;
        e >>= 1;
    }
    float E = fmaf(W, wdec, Sx);

    float f = 0.8f * E;
    float* qp = g_q + ((size_t)b * TT + t0) * 8 + j;
    qp[0]  = l0 + f; f *= 0.8f;
    qp[8]  = l1 + f; f *= 0.8f;
    qp[16] = l2 + f; f *= 0.8f;
    qp[24] = l3 + f;
}

// ---------------------------------------------------------------------------
// K5: streaming traj assembly. CHANGE vs R13: chunk's q block (64 t x 8)
// staged in shared memory once -> main loop has zero LDG on the q path.
// ---------------------------------------------------------------------------
__global__ void __launch_bounds__(128) k_trajA(const float* __restrict__ L,
                                               float* __restrict__ traj,
                                               float* __restrict__ xlast)
{
    __shared__ __align__(16) float qs[64 * 8];     // 2KB: q rows for this chunk
    const int b     = blockIdx.x;
    const int chunk = blockIdx.y;
    const int h4    = threadIdx.x;
    const float KC = 0.2f / ((float)TH * (float)TH);

    float4 La[4], Lb[4];
#pragma unroll
    for (int i = 0; i < 4; i++) {
        La[i] = *(const float4*)(L + (size_t)(4 * h4 + i) * TR);
        Lb[i] = *(const float4*)(L + (size_t)(4 * h4 + i) * TR + 4);
    }

    const int t0 = chunk * 64;
    const int tend = t0 + 64;

    // stage q[t0..t0+63][0..7] into smem (512 floats, coalesced)
    {
        const float* qsrc = g_q + ((size_t)b * TT + t0) * 8;
#pragma unroll
        for (int s = 0; s < 4; s++)
            qs[h4 + s * 128] = qsrc[h4 + s * 128];
    }
    __syncthreads();

    const size_t s4 = (size_t)TB * TH / 4;
    const float4* xp = (const float4*)g_X + (size_t)(TB + b) * (TH / 4) + h4;
    float4* tp = (float4*)traj + ((size_t)b * TT) * (TH / 4) + h4;

    float4 xr[8];
#pragma unroll
    for (int p = 0; p < 8; p++)
        xr[p] = xp[(size_t)(t0 + p) * s4];

    for (int t = t0; t < tend; t += 8) {
#pragma unroll
        for (int k = 0; k < 8; k++) {
            const int tt = t + k;
            const float* qp = qs + (tt - t0) * 8;   // broadcast LDS
            float4 q0 = *(const float4*)qp;
            float4 q1 = *(const float4*)(qp + 4);

            float4 xt = xr[k];
            float4 tv;
            float e0 = La[0].x * q0.x;
            e0 = fmaf(La[0].y, q0.y, e0); e0 = fmaf(La[0].z, q0.z, e0);
            e0 = fmaf(La[0].w, q0.w, e0); e0 = fmaf(Lb[0].x, q1.x, e0);
            e0 = fmaf(Lb[0].y, q1.y, e0); e0 = fmaf(Lb[0].z, q1.z, e0);
            e0 = fmaf(Lb[0].w, q1.w, e0);
            tv.x = fmaf(KC, e0, xt.x);
            float e1 = La[1].x * q0.x;
            e1 = fmaf(La[1].y, q0.y, e1); e1 = fmaf(La[1].z, q0.z, e1);
            e1 = fmaf(La[1].w, q0.w, e1); e1 = fmaf(Lb[1].x, q1.x, e1);
            e1 = fmaf(Lb[1].y, q1.y, e1); e1 = fmaf(Lb[1].z, q1.z, e1);
            e1 = fmaf(Lb[1].w, q1.w, e1);
            tv.y = fmaf(KC, e1, xt.y);
            float e2 = La[2].x * q0.x;
            e2 = fmaf(La[2].y, q0.y, e2); e2 = fmaf(La[2].z, q0.z, e2);
            e2 = fmaf(La[2].w, q0.w, e2); e2 = fmaf(Lb[2].x, q1.x, e2);
            e2 = fmaf(Lb[2].y, q1.y, e2); e2 = fmaf(Lb[2].z, q1.z, e2);
            e2 = fmaf(Lb[2].w, q1.w, e2);
            tv.z = fmaf(KC, e2, xt.z);
            float e3 = La[3].x * q0.x;
            e3 = fmaf(La[3].y, q0.y, e3); e3 = fmaf(La[3].z, q0.z, e3);
            e3 = fmaf(La[3].w, q0.w, e3); e3 = fmaf(Lb[3].x, q1.x, e3);
            e3 = fmaf(Lb[3].y, q1.y, e3); e3 = fmaf(Lb[3].z, q1.z, e3);
            e3 = fmaf(Lb[3].w, q1.w, e3);
            tv.w = fmaf(KC, e3, xt.w);

            tp[(size_t)tt * (TH / 4)] = tv;
            if (tt == TT - 1)
                *((float4*)xlast + (size_t)b * (TH / 4) + h4) = tv;
            if (tt + 8 < tend) xr[k] = xp[(size_t)(tt + 8) * s4];
        }
    }
}

// ---------------------------------------------------------------------------
// K6: readout GEMM, 128-row tiles (R13 version, ~140us)
// ---------------------------------------------------------------------------
__global__ void __launch_bounds__(256) k_out(const float* __restrict__ traj,
                                             const float* __restrict__ W_out,
                                             const float* __restrict__ b_out,
                                             float* __restrict__ outp)
{
    __shared__ __align__(16) float at[64 * 128];
    __shared__ __align__(16) float bs2[64 * 64];
    const int bm  = blockIdx.x;
    const int tid = threadIdx.x;
    const int tx = tid & 15;
    const int ty = tid >> 4;

    ull acc[8][2];
#pragma unroll
    for (int i = 0; i < 8; i++) { acc[i][0] = 0ull; acc[i][1] = 0ull; }

    for (int kc = 0; kc < 8; kc++) {
        __syncthreads();
#pragma unroll
        for (int s = 0; s < 32; s++) {
            int i = tid + s * 256;
            int r = i >> 6;
            int k = i & 63;
            int sw = (k & 15) << 2;
            float tv = traj[((size_t)(bm * 128 + r)) * TH + kc * 64 + k];
            at[k * 128 + (r ^ sw)] = acc_tanh(tv);
        }
#pragma unroll
        for (int s = 0; s < 16; s++) {
            int i = tid + s * 256;
            int r = i >> 6;
            int k = i & 63;
            int sw = (k & 15) << 2;
            bs2[k * 64 + (r ^ sw)] = W_out[(size_t)r * TH + kc * 64 + k];
        }
        __syncthreads();
#pragma unroll
        for (int k = 0; k < 64; k++) {
            int swk = (k & 15) << 2;
            float4 a0 = *(const float4*)&at[k * 128 + ((ty * 8) ^ swk)];
            float4 a1 = *(const float4*)&at[k * 128 + (((ty * 8) ^ swk) ^ 4)];
            ulonglong2 w2 = *(const ulonglong2*)&bs2[k * 64 + ((tx * 4) ^ swk)];
            ull d0 = dup2(a0.x), d1 = dup2(a0.y), d2 = dup2(a0.z), d3 = dup2(a0.w);
            ull d4 = dup2(a1.x), d5 = dup2(a1.y), d6 = dup2(a1.z), d7 = dup2(a1.w);
            fma2(acc[0][0], d0, w2.x); fma2(acc[0][1], d0, w2.y);
            fma2(acc[1][0], d1, w2.x); fma2(acc[1][1], d1, w2.y);
            fma2(acc[2][0], d2, w2.x); fma2(acc[2][1], d2, w2.y);
            fma2(acc[3][0], d3, w2.x); fma2(acc[3][1], d3, w2.y);
            fma2(acc[4][0], d4, w2.x); fma2(acc[4][1], d4, w2.y);
            fma2(acc[5][0], d5, w2.x); fma2(acc[5][1], d5, w2.y);
            fma2(acc[6][0], d6, w2.x); fma2(acc[6][1], d6, w2.y);
            fma2(acc[7][0], d7, w2.x); fma2(acc[7][1], d7, w2.y);
        }
    }

    const int o0 = tx * 4;
    float4 bias = *(const float4*)&b_out[o0];
#pragma unroll
    for (int i = 0; i < 8; i++) {
        int m = bm * 128 + ty * 8 + i;
        float v0, v1, v2, v3;
        unpack2(acc[i][0], v0, v1);
        unpack2(acc[i][1], v2, v3);
        float4 o;
        o.x = v0 + bias.x; o.y = v1 + bias.y;
        o.z = v2 + bias.z; o.w = v3 + bias.w;
        *(float4*)&outp[(size_t)m * TO + o0] = o;
    }
}

// ---------------------------------------------------------------------------
// Launcher. Inputs: u, x0, noise, L, M, N, W_in, b_in, W_out, b_out.
// Output: [output | x_last | traj].
// Chain: xcopy(1) -> inp(2) -> scanA(3) -> recg(4, profiled) -> qscan(5)
//        -> trajA(6) -> out(7).
// ---------------------------------------------------------------------------
extern "C" void kernel_launch(void* const* d_in, const int* in_sizes, int n_in,
                              void* d_out, int out_size)
{
    (void)in_sizes; (void)n_in; (void)out_size;
    const float* u     = (const float*)d_in[0];
    const float* x0    = (const float*)d_in[1];
    const float* noise = (const float*)d_in[2];
    const float* L     = (const float*)d_in[3];
    const float* Mw    = (const float*)d_in[4];
    const float* Nw    = (const float*)d_in[5];
    const float* W_in  = (const float*)d_in[6];
    const float* b_in  = (const float*)d_in[7];
    const float* W_out = (const float*)d_in[8];
    const float* b_out = (const float*)d_in[9];

    float* outp  = (float*)d_out;
    float* xlast = outp + (size_t)TB * TT * TO;
    float* traj  = xlast + (size_t)TB * TH;

    k_xcopy<<<32, 256>>>(x0);
    k_inp<<<dim3(512, 8), 256>>>(u, W_in, b_in, noise);
    k_scanA<<<dim3(64, 16), 128>>>(x0);
    k_recg<<<512, 128>>>(Mw, Nw);
    k_qscan<<<512, 256>>>();
    k_trajA<<<dim3(64, 16), 128>>>(L, traj, xlast);
    k_out<<<(TB * TT) / 128, 256>>>(traj, W_out, b_out, outp);
}